// round 1
// baseline (speedup 1.0000x reference)
#include <cuda_runtime.h>

// ---------------- problem constants ----------------
#define NB    32          // batch
#define CC    128         // cell channels
#define CIN   512         // input channels
#define HW    1024        // 32*32
#define PLANE (CC*HW)     // 131072 floats per (batch, state)
#define NMIX  14
#define BNS   0.9999950000374997f   // 1/sqrt(1+1e-5)

// ---------------- device scratch (static, allocation-free) ----------------
__device__ __align__(16) float g_s0[NB*PLANE];
__device__ __align__(16) float g_s1[NB*PLANE];
__device__ __align__(16) float g_t0[NB*PLANE];
__device__ __align__(16) float g_t1[NB*PLANE];
__device__ __align__(16) float g_t2[NB*PLANE];
__device__ __align__(16) float g_t3[NB*PLANE];
__device__ __align__(16) float g_u0[NB*PLANE];
__device__ __align__(16) float g_u1[NB*PLANE];
__device__ __align__(16) float g_v0[NB*PLANE];
__device__ __align__(16) float g_v1[NB*PLANE];
__device__ __align__(16) float g_pw[NMIX*NB*8];

// ---------------- gate kernel: top-2 + masked softmax ----------------
__global__ void gate_kernel(const float* __restrict__ gates, float* __restrict__ P) {
    int idx = blockIdx.x * blockDim.x + threadIdx.x;
    if (idx >= NMIX * NB) return;
    const float* g = gates + idx * 8;
    float gv[8];
#pragma unroll
    for (int j = 0; j < 8; j++) gv[j] = g[j];
    bool sel[8] = {false, false, false, false, false, false, false, false};
    // top = 2 (fixed by setup_inputs)
    for (int t = 0; t < 2; t++) {
        int best = -1; float bv = -3.4e38f;
#pragma unroll
        for (int j = 0; j < 8; j++)
            if (!sel[j] && gv[j] > bv) { bv = gv[j]; best = j; }
        sel[best] = true;
    }
    float mx = -3.4e38f;
#pragma unroll
    for (int j = 0; j < 8; j++) if (sel[j]) mx = fmaxf(mx, gv[j]);
    float e[8]; float s = 0.f;
#pragma unroll
    for (int j = 0; j < 8; j++) { e[j] = sel[j] ? expf(gv[j] - mx) : 0.f; s += e[j]; }
#pragma unroll
    for (int j = 0; j < 8; j++) P[idx * 8 + j] = e[j] / s;
}

// ---------------- fused pool/skip kernel ----------------
// out += p1*BN*maxpool3(x) + p2*BN*avgpool3(x,count_excl_pad) + p3*x
__global__ __launch_bounds__(256) void pool_kernel(
    const float* __restrict__ X, long bsX,
    float* __restrict__ O, long bsO,
    const float* __restrict__ Pm)
{
    int c = blockIdx.x, b = blockIdx.y, tid = threadIdx.x;
    float p1 = Pm[b*8+1], p2 = Pm[b*8+2], p3 = Pm[b*8+3];
    if (p1 == 0.f && p2 == 0.f && p3 == 0.f) return;
    __shared__ float st[1024];
    const float* xp = X + (long)b * bsX + c * HW;
    for (int i = tid; i < 1024; i += 256) st[i] = xp[i];
    __syncthreads();
    float* op = O + (long)b * bsO + c * HW;
    for (int px = tid; px < 1024; px += 256) {
        int y = px >> 5, x = px & 31;
        float mx = -3.4e38f, s = 0.f; int cnt = 0;
#pragma unroll
        for (int dy = -1; dy <= 1; dy++) {
            int yy = y + dy;
            if (yy < 0 || yy > 31) continue;
#pragma unroll
            for (int dx = -1; dx <= 1; dx++) {
                int xx = x + dx;
                if (xx < 0 || xx > 31) continue;
                float v = st[yy * 32 + xx];
                mx = fmaxf(mx, v); s += v; cnt++;
            }
        }
        float res = p1 * (BNS * mx) + p2 * (BNS * (s / (float)cnt)) + p3 * st[px];
        op[px] += res;
    }
}

// ---------------- fused multi-branch depthwise conv ----------------
struct DwArgs {
    const float* X[4]; long bsX[4];
    const float* W[4];
    float*       Y[4];
    const float* P[4];   // gating ptr (stride 8 per batch sample)
    int ks[4], dil[4];
};

template<int KS, int DIL, int PAD>
__device__ __forceinline__ void dw_inner(const float* __restrict__ st,
                                         const float* __restrict__ w,
                                         float* __restrict__ yp, int tid)
{
    for (int px = tid; px < 1024; px += 256) {
        int y = px >> 5, x = px & 31;
        const float* base = st + (y + 4 - PAD) * 40 + (x + 4 - PAD);
        float acc = 0.f;
#pragma unroll
        for (int i = 0; i < KS; i++)
#pragma unroll
            for (int j = 0; j < KS; j++)
                acc += w[i * KS + j] * base[i * DIL * 40 + j * DIL];
        yp[px] = acc;
    }
}

__global__ __launch_bounds__(256) void dw_kernel(DwArgs da) {
    int br = blockIdx.z, b = blockIdx.y, c = blockIdx.x;
    const float* gp = da.P[br];
    if (gp && gp[b * 8] == 0.f) return;
    __shared__ float st[1600];  // 40x40, relu(x) with zero halo (max pad 4)
    int tid = threadIdx.x;
    for (int i = tid; i < 1600; i += 256) st[i] = 0.f;
    __syncthreads();
    const float* xp = da.X[br] + (long)b * da.bsX[br] + c * HW;
    for (int i = tid; i < 1024; i += 256) {
        int y = i >> 5, x = i & 31;
        st[(y + 4) * 40 + x + 4] = fmaxf(xp[i], 0.f);
    }
    __syncthreads();
    int ks = da.ks[br];
    int ksz = ks * ks;
    const float* wp = da.W[br] + c * ksz;
    float w[25];
#pragma unroll
    for (int i = 0; i < 25; i++) {
        if (i < ksz) w[i] = wp[i]; else w[i] = 0.f;
    }
    float* yp = da.Y[br] + (long)b * PLANE + c * HW;
    int dil = da.dil[br];
    if (ks == 3 && dil == 1)      dw_inner<3,1,1>(st, w, yp, tid);
    else if (ks == 5 && dil == 1) dw_inner<5,1,2>(st, w, yp, tid);
    else if (ks == 3)             dw_inner<3,2,2>(st, w, yp, tid);
    else                          dw_inner<5,2,4>(st, w, yp, tid);
}

// ---------------- fused multi-branch 128xN GEMM (pointwise conv) ----------------
// C[b][o][px] (+)= scale * sum_k A[o][k] * (relu?)(B[b][k][px])
struct GemmArgs {
    const float* A[4];
    const float* B[4];
    float*       Cp[4];
    const float* P[4];     // gating/scale ptr (stride 8), null => always run
    float        cscale[4];
    int          byP[4];   // multiply scale by per-sample gate weight
    int          accum[4]; // atomicAdd epilogue
    long         bsB[4];
    long         bsC[4];
    int          K;
    int          reluB;
};

__global__ __launch_bounds__(256) void gemm128(GemmArgs ga) {
    int br = blockIdx.z, b = blockIdx.y;
    const float* gp = ga.P[br];
    float pv = 1.f;
    if (gp) { pv = gp[b * 8]; if (pv == 0.f) return; }
    float scale = ga.cscale[br] * (ga.byP[br] ? pv : 1.f);
    const float* A = ga.A[br];
    const float* Bm = ga.B[br] + (long)b * ga.bsB[br] + blockIdx.x * 128;
    float* Cm = ga.Cp[br] + (long)b * ga.bsC[br] + blockIdx.x * 128;
    int K = ga.K;
    int reluB = ga.reluB;

    __shared__ float As[16][128];
    __shared__ float Bs[16][128];

    int tid  = threadIdx.x;
    int arow = tid >> 1,  akoff = (tid & 1) * 8;
    int bk   = tid >> 4,  bcoff = (tid & 15) * 8;
    int tx   = tid & 15,  ty    = tid >> 4;

    float acc[8][8];
#pragma unroll
    for (int i = 0; i < 8; i++)
#pragma unroll
        for (int j = 0; j < 8; j++) acc[i][j] = 0.f;

    for (int k0 = 0; k0 < K; k0 += 16) {
        float4 a0 = *(const float4*)(A + (long)arow * K + k0 + akoff);
        float4 a1 = *(const float4*)(A + (long)arow * K + k0 + akoff + 4);
        As[akoff + 0][arow] = a0.x; As[akoff + 1][arow] = a0.y;
        As[akoff + 2][arow] = a0.z; As[akoff + 3][arow] = a0.w;
        As[akoff + 4][arow] = a1.x; As[akoff + 5][arow] = a1.y;
        As[akoff + 6][arow] = a1.z; As[akoff + 7][arow] = a1.w;

        float4 b0 = *(const float4*)(Bm + (long)(k0 + bk) * HW + bcoff);
        float4 b1 = *(const float4*)(Bm + (long)(k0 + bk) * HW + bcoff + 4);
        if (reluB) {
            b0.x = fmaxf(b0.x, 0.f); b0.y = fmaxf(b0.y, 0.f);
            b0.z = fmaxf(b0.z, 0.f); b0.w = fmaxf(b0.w, 0.f);
            b1.x = fmaxf(b1.x, 0.f); b1.y = fmaxf(b1.y, 0.f);
            b1.z = fmaxf(b1.z, 0.f); b1.w = fmaxf(b1.w, 0.f);
        }
        *(float4*)&Bs[bk][bcoff]     = b0;
        *(float4*)&Bs[bk][bcoff + 4] = b1;
        __syncthreads();

#pragma unroll
        for (int kk = 0; kk < 16; kk++) {
            float4 av0 = *(const float4*)&As[kk][ty * 8];
            float4 av1 = *(const float4*)&As[kk][ty * 8 + 4];
            float4 bv0 = *(const float4*)&Bs[kk][tx * 8];
            float4 bv1 = *(const float4*)&Bs[kk][tx * 8 + 4];
            float ar[8] = {av0.x, av0.y, av0.z, av0.w, av1.x, av1.y, av1.z, av1.w};
            float brr[8] = {bv0.x, bv0.y, bv0.z, bv0.w, bv1.x, bv1.y, bv1.z, bv1.w};
#pragma unroll
            for (int i = 0; i < 8; i++)
#pragma unroll
                for (int j = 0; j < 8; j++)
                    acc[i][j] += ar[i] * brr[j];
        }
        __syncthreads();
    }

    if (ga.accum[br]) {
#pragma unroll
        for (int i = 0; i < 8; i++) {
            float* crow = Cm + (long)(ty * 8 + i) * HW + tx * 8;
#pragma unroll
            for (int j = 0; j < 8; j++)
                atomicAdd(&crow[j], scale * acc[i][j]);
        }
    } else {
#pragma unroll
        for (int i = 0; i < 8; i++) {
            float* crow = Cm + (long)(ty * 8 + i) * HW + tx * 8;
            float4 v0 = make_float4(scale * acc[i][0], scale * acc[i][1],
                                    scale * acc[i][2], scale * acc[i][3]);
            float4 v1 = make_float4(scale * acc[i][4], scale * acc[i][5],
                                    scale * acc[i][6], scale * acc[i][7]);
            *(float4*)&crow[0] = v0;
            *(float4*)&crow[4] = v1;
        }
    }
}

// ---------------- host orchestration ----------------
extern "C" void kernel_launch(void* const* d_in, const int* in_sizes, int n_in,
                              void* d_out, int out_size) {
    const float* s0r   = (const float*)d_in[0];
    const float* s1r   = (const float*)d_in[1];
    const float* gates = (const float*)d_in[2];
    const float* pre0  = (const float*)d_in[3];
    const float* pre1  = (const float*)d_in[4];
    const float* s3d1  = (const float*)d_in[5];
    const float* s3p1  = (const float*)d_in[6];
    const float* s3d2  = (const float*)d_in[7];
    const float* s3p2  = (const float*)d_in[8];
    const float* s5d1  = (const float*)d_in[9];
    const float* s5p1  = (const float*)d_in[10];
    const float* s5d2  = (const float*)d_in[11];
    const float* s5p2  = (const float*)d_in[12];
    const float* d3d   = (const float*)d_in[13];
    const float* d3p   = (const float*)d_in[14];
    const float* d5d   = (const float*)d_in[15];
    const float* d5p   = (const float*)d_in[16];
    float* out = (float*)d_out;

    float *ps0, *ps1, *pt0, *pt1, *pt2, *pt3, *pu0, *pu1, *pv0, *pv1, *pp;
    cudaGetSymbolAddress((void**)&ps0, g_s0);
    cudaGetSymbolAddress((void**)&ps1, g_s1);
    cudaGetSymbolAddress((void**)&pt0, g_t0);
    cudaGetSymbolAddress((void**)&pt1, g_t1);
    cudaGetSymbolAddress((void**)&pt2, g_t2);
    cudaGetSymbolAddress((void**)&pt3, g_t3);
    cudaGetSymbolAddress((void**)&pu0, g_u0);
    cudaGetSymbolAddress((void**)&pu1, g_u1);
    cudaGetSymbolAddress((void**)&pv0, g_v0);
    cudaGetSymbolAddress((void**)&pv1, g_v1);
    cudaGetSymbolAddress((void**)&pp,  g_pw);

    cudaMemsetAsync(d_out, 0, (size_t)out_size * sizeof(float), 0);
    gate_kernel<<<2, 256>>>(gates, pp);

    // preprocess: s0/s1 -> states 0/1 (ReLU -> 1x1 conv 512->128 -> BN)
    {
        GemmArgs pa = {};
        pa.K = CIN; pa.reluB = 1;
        pa.A[0] = pre0; pa.B[0] = s0r; pa.Cp[0] = ps0; pa.P[0] = nullptr;
        pa.cscale[0] = BNS; pa.byP[0] = 0; pa.accum[0] = 0;
        pa.bsB[0] = (long)CIN * HW; pa.bsC[0] = PLANE;
        pa.A[1] = pre1; pa.B[1] = s1r; pa.Cp[1] = ps1; pa.P[1] = nullptr;
        pa.cscale[1] = BNS; pa.byP[1] = 0; pa.accum[1] = 0;
        pa.bsB[1] = (long)CIN * HW; pa.bsC[1] = PLANE;
        gemm128<<<dim3(8, NB, 2), 256>>>(pa);
    }

    struct StateDesc { float* p; long bs; };
    StateDesc st[6] = {
        {ps0, (long)PLANE}, {ps1, (long)PLANE},
        {out,             512L * HW}, {out + PLANE,     512L * HW},
        {out + 2 * PLANE, 512L * HW}, {out + 3 * PLANE, 512L * HW}
    };

    const float* dw1w[4] = {s3d1, s5d1, d3d, d5d};
    const long   dw1sz[4] = {9, 25, 9, 25};
    const int    dwk[4]  = {3, 5, 3, 5};
    const int    dwdil[4] = {1, 1, 2, 2};
    float*       tbuf[4] = {pt0, pt1, pt2, pt3};

    int m = 0;
    for (int i = 0; i < 4; i++) {
        StateDesc dst = st[2 + i];
        for (int j = 0; j < 2 + i; j++, m++) {
            StateDesc src = st[j];
            const float* gp = pp + (long)m * NB * 8;

            // pools + skip
            pool_kernel<<<dim3(CC, NB), 256>>>(src.p, src.bs, dst.p, dst.bs, gp);

            // first depthwise stage: sep3_dw1, sep5_dw1, dil3_dw, dil5_dw
            DwArgs d1 = {};
            for (int br = 0; br < 4; br++) {
                d1.X[br] = src.p; d1.bsX[br] = src.bs;
                d1.W[br] = dw1w[br] + (long)m * CC * dw1sz[br];
                d1.Y[br] = tbuf[br];
                d1.P[br] = gp + 4 + br;
                d1.ks[br] = dwk[br]; d1.dil[br] = dwdil[br];
            }
            dw_kernel<<<dim3(CC, NB, 4), 256>>>(d1);

            // first pointwise stage: sep pw1 (store), dil pw (scaled accumulate)
            GemmArgs g1 = {};
            g1.K = CC; g1.reluB = 0;
            g1.A[0] = s3p1 + (long)m * CC * CC; g1.B[0] = pt0; g1.Cp[0] = pu0;
            g1.P[0] = gp + 4; g1.cscale[0] = BNS; g1.byP[0] = 0; g1.accum[0] = 0;
            g1.bsB[0] = PLANE; g1.bsC[0] = PLANE;
            g1.A[1] = s5p1 + (long)m * CC * CC; g1.B[1] = pt1; g1.Cp[1] = pu1;
            g1.P[1] = gp + 5; g1.cscale[1] = BNS; g1.byP[1] = 0; g1.accum[1] = 0;
            g1.bsB[1] = PLANE; g1.bsC[1] = PLANE;
            g1.A[2] = d3p + (long)m * CC * CC; g1.B[2] = pt2; g1.Cp[2] = dst.p;
            g1.P[2] = gp + 6; g1.cscale[2] = BNS; g1.byP[2] = 1; g1.accum[2] = 1;
            g1.bsB[2] = PLANE; g1.bsC[2] = dst.bs;
            g1.A[3] = d5p + (long)m * CC * CC; g1.B[3] = pt3; g1.Cp[3] = dst.p;
            g1.P[3] = gp + 7; g1.cscale[3] = BNS; g1.byP[3] = 1; g1.accum[3] = 1;
            g1.bsB[3] = PLANE; g1.bsC[3] = dst.bs;
            gemm128<<<dim3(8, NB, 4), 256>>>(g1);

            // second depthwise stage: sep3_dw2, sep5_dw2 (input relu(u))
            DwArgs d2 = {};
            d2.X[0] = pu0; d2.bsX[0] = PLANE;
            d2.W[0] = s3d2 + (long)m * CC * 9;  d2.Y[0] = pv0;
            d2.P[0] = gp + 4; d2.ks[0] = 3; d2.dil[0] = 1;
            d2.X[1] = pu1; d2.bsX[1] = PLANE;
            d2.W[1] = s5d2 + (long)m * CC * 25; d2.Y[1] = pv1;
            d2.P[1] = gp + 5; d2.ks[1] = 5; d2.dil[1] = 1;
            dw_kernel<<<dim3(CC, NB, 2), 256>>>(d2);

            // second pointwise stage: sep pw2 -> scaled accumulate into dst
            GemmArgs g2 = {};
            g2.K = CC; g2.reluB = 0;
            g2.A[0] = s3p2 + (long)m * CC * CC; g2.B[0] = pv0; g2.Cp[0] = dst.p;
            g2.P[0] = gp + 4; g2.cscale[0] = BNS; g2.byP[0] = 1; g2.accum[0] = 1;
            g2.bsB[0] = PLANE; g2.bsC[0] = dst.bs;
            g2.A[1] = s5p2 + (long)m * CC * CC; g2.B[1] = pv1; g2.Cp[1] = dst.p;
            g2.P[1] = gp + 5; g2.cscale[1] = BNS; g2.byP[1] = 1; g2.accum[1] = 1;
            g2.bsB[1] = PLANE; g2.bsC[1] = dst.bs;
            gemm128<<<dim3(8, NB, 2), 256>>>(g2);
        }
    }
}

// round 2
// speedup vs baseline: 1.3370x; 1.3370x over previous
#include <cuda_runtime.h>

// ---------------- problem constants ----------------
#define NB    32          // batch
#define CC    128         // cell channels
#define CIN   512         // input channels
#define HW    1024        // 32*32
#define PLANE (CC*HW)     // 131072 floats per (batch, state)
#define NBPLANE (NB*PLANE)
#define NMIX  14
#define BNS   0.9999950000374997f   // 1/sqrt(1+1e-5)

// ---------------- device scratch (static, allocation-free) ----------------
__device__ __align__(16) float g_s0[NBPLANE];
__device__ __align__(16) float g_s1[NBPLANE];
__device__ __align__(16) float g_t[20L * NBPLANE];   // dw1 outputs (and dw2 outputs, aliased)
__device__ __align__(16) float g_u[10L * NBPLANE];   // sep pw1 outputs
__device__ __align__(16) float g_pw[NMIX * NB * 8];

// ---------------- gate kernel: top-2 + masked softmax ----------------
__global__ void gate_kernel(const float* __restrict__ gates, float* __restrict__ P) {
    int idx = blockIdx.x * blockDim.x + threadIdx.x;
    if (idx >= NMIX * NB) return;
    const float* g = gates + idx * 8;
    float gv[8];
#pragma unroll
    for (int j = 0; j < 8; j++) gv[j] = g[j];
    bool sel[8] = {false, false, false, false, false, false, false, false};
    for (int t = 0; t < 2; t++) {      // top = 2 fixed by setup_inputs
        int best = -1; float bv = -3.4e38f;
#pragma unroll
        for (int j = 0; j < 8; j++)
            if (!sel[j] && gv[j] > bv) { bv = gv[j]; best = j; }
        sel[best] = true;
    }
    float mx = -3.4e38f;
#pragma unroll
    for (int j = 0; j < 8; j++) if (sel[j]) mx = fmaxf(mx, gv[j]);
    float e[8]; float s = 0.f;
#pragma unroll
    for (int j = 0; j < 8; j++) { e[j] = sel[j] ? expf(gv[j] - mx) : 0.f; s += e[j]; }
#pragma unroll
    for (int j = 0; j < 8; j++) P[idx * 8 + j] = e[j] / s;
}

// ---------------- fused pool/skip kernel (loops over all j of a step) ----------------
struct PoolArgs {
    const float* X[5]; long bsX[5];
    const float* P[5];
    float* O; long bsO;
    int nj;
};

__global__ __launch_bounds__(256) void pool_kernel(PoolArgs pa) {
    int c = blockIdx.x, b = blockIdx.y, tid = threadIdx.x;
    __shared__ float st[1024];
    float acc[4] = {0.f, 0.f, 0.f, 0.f};
    for (int j = 0; j < pa.nj; j++) {
        const float* pj = pa.P[j] + b * 8;
        float p1 = pj[1], p2 = pj[2], p3 = pj[3];
        if (p1 == 0.f && p2 == 0.f && p3 == 0.f) continue;   // uniform over block
        __syncthreads();
        const float* xp = pa.X[j] + (long)b * pa.bsX[j] + c * HW;
        for (int i = tid; i < 1024; i += 256) st[i] = xp[i];
        __syncthreads();
#pragma unroll
        for (int q = 0; q < 4; q++) {
            int px = tid + q * 256;
            int y = px >> 5, x = px & 31;
            float mx = -3.4e38f, s = 0.f; int cnt = 0;
#pragma unroll
            for (int dy = -1; dy <= 1; dy++) {
                int yy = y + dy;
                if (yy < 0 || yy > 31) continue;
#pragma unroll
                for (int dx = -1; dx <= 1; dx++) {
                    int xx = x + dx;
                    if (xx < 0 || xx > 31) continue;
                    float v = st[yy * 32 + xx];
                    mx = fmaxf(mx, v); s += v; cnt++;
                }
            }
            acc[q] += p1 * (BNS * mx) + p2 * (BNS * (s / (float)cnt)) + p3 * st[px];
        }
    }
    float* op = pa.O + (long)b * pa.bsO + c * HW;
#pragma unroll
    for (int q = 0; q < 4; q++) op[tid + q * 256] = acc[q];   // sole writer pre-GEMM
}

// ---------------- fused multi-entry depthwise conv ----------------
struct DwArgs {
    const float* X[20]; long bsX[20];
    const float* W[20];
    float*       Y[20];
    const float* P[20];
    int ks[20], dil[20];
};

template<int KS, int DIL, int PAD>
__device__ __forceinline__ void dw_inner(const float* __restrict__ st,
                                         const float* __restrict__ w,
                                         float* __restrict__ yp, int tid)
{
    for (int px = tid; px < 1024; px += 256) {
        int y = px >> 5, x = px & 31;
        const float* base = st + (y + 4 - PAD) * 40 + (x + 4 - PAD);
        float acc = 0.f;
#pragma unroll
        for (int i = 0; i < KS; i++)
#pragma unroll
            for (int j = 0; j < KS; j++)
                acc += w[i * KS + j] * base[i * DIL * 40 + j * DIL];
        yp[px] = acc;
    }
}

__global__ __launch_bounds__(256) void dw_kernel(DwArgs da) {
    int e = blockIdx.z, b = blockIdx.y, c = blockIdx.x;
    if (da.P[e][b * 8] == 0.f) return;
    __shared__ float st[1600];  // 40x40, relu(x) with zero halo (max pad 4)
    int tid = threadIdx.x;
    for (int i = tid; i < 1600; i += 256) st[i] = 0.f;
    __syncthreads();
    const float* xp = da.X[e] + (long)b * da.bsX[e] + c * HW;
    for (int i = tid; i < 1024; i += 256) {
        int y = i >> 5, x = i & 31;
        st[(y + 4) * 40 + x + 4] = fmaxf(xp[i], 0.f);
    }
    __syncthreads();
    int ks = da.ks[e];
    int ksz = ks * ks;
    const float* wp = da.W[e] + c * ksz;
    float w[25];
#pragma unroll
    for (int i = 0; i < 25; i++) w[i] = (i < ksz) ? wp[i] : 0.f;
    float* yp = da.Y[e] + (long)b * PLANE + c * HW;
    int dil = da.dil[e];
    if (ks == 3 && dil == 1)      dw_inner<3,1,1>(st, w, yp, tid);
    else if (ks == 5 && dil == 1) dw_inner<5,1,2>(st, w, yp, tid);
    else if (ks == 3)             dw_inner<3,2,2>(st, w, yp, tid);
    else                          dw_inner<5,2,4>(st, w, yp, tid);
}

// ---------------- fused multi-entry 128x128 GEMM (pointwise conv), double-buffered ----------------
struct GemmArgs {
    const float* A[20];
    const float* B[20];
    float*       Cp[20];
    const float* P[20];
    float        cscale[20];
    int          byP[20];
    int          accum[20];
    long         bsB[20];
    long         bsC[20];
    int          K;
    int          reluB;
};

__global__ __launch_bounds__(256, 2) void gemm128(GemmArgs ga) {
    int e = blockIdx.z, b = blockIdx.y;
    const float* gp = ga.P[e];
    float pv = 1.f;
    if (gp) { pv = gp[b * 8]; if (pv == 0.f) return; }
    float scale = ga.cscale[e] * (ga.byP[e] ? pv : 1.f);
    const int K = ga.K;
    const int reluB = ga.reluB;

    __shared__ float As[2][16][128];
    __shared__ float Bs[2][16][128];

    int tid  = threadIdx.x;
    int arow = tid >> 1,  akoff = (tid & 1) * 8;
    int bk   = tid >> 4,  bcoff = (tid & 15) * 8;
    int tx   = tid & 15,  ty    = tid >> 4;

    const float* Aptr = ga.A[e] + (long)arow * K + akoff;
    const float* Bptr = ga.B[e] + (long)b * ga.bsB[e] + blockIdx.x * 128
                        + (long)bk * HW + bcoff;
    float* Cm = ga.Cp[e] + (long)b * ga.bsC[e] + blockIdx.x * 128;

    float acc[8][8];
#pragma unroll
    for (int i = 0; i < 8; i++)
#pragma unroll
        for (int j = 0; j < 8; j++) acc[i][j] = 0.f;

    // prologue: tile 0 -> buffer 0
    {
        float4 a0 = *(const float4*)(Aptr);
        float4 a1 = *(const float4*)(Aptr + 4);
        float4 b0 = *(const float4*)(Bptr);
        float4 b1 = *(const float4*)(Bptr + 4);
        if (reluB) {
            b0.x = fmaxf(b0.x, 0.f); b0.y = fmaxf(b0.y, 0.f);
            b0.z = fmaxf(b0.z, 0.f); b0.w = fmaxf(b0.w, 0.f);
            b1.x = fmaxf(b1.x, 0.f); b1.y = fmaxf(b1.y, 0.f);
            b1.z = fmaxf(b1.z, 0.f); b1.w = fmaxf(b1.w, 0.f);
        }
        As[0][akoff + 0][arow] = a0.x; As[0][akoff + 1][arow] = a0.y;
        As[0][akoff + 2][arow] = a0.z; As[0][akoff + 3][arow] = a0.w;
        As[0][akoff + 4][arow] = a1.x; As[0][akoff + 5][arow] = a1.y;
        As[0][akoff + 6][arow] = a1.z; As[0][akoff + 7][arow] = a1.w;
        *(float4*)&Bs[0][bk][bcoff]     = b0;
        *(float4*)&Bs[0][bk][bcoff + 4] = b1;
    }

    const int T = K >> 4;
    int cur = 0;
    for (int t = 0; t < T; t++) {
        __syncthreads();
        float4 na0, na1, nb0, nb1;
        bool more = (t + 1 < T);
        if (more) {
            na0 = *(const float4*)(Aptr + (t + 1) * 16);
            na1 = *(const float4*)(Aptr + (t + 1) * 16 + 4);
            nb0 = *(const float4*)(Bptr + (long)(t + 1) * 16 * HW);
            nb1 = *(const float4*)(Bptr + (long)(t + 1) * 16 * HW + 4);
        }
#pragma unroll
        for (int kk = 0; kk < 16; kk++) {
            float4 av0 = *(const float4*)&As[cur][kk][ty * 8];
            float4 av1 = *(const float4*)&As[cur][kk][ty * 8 + 4];
            float4 bv0 = *(const float4*)&Bs[cur][kk][tx * 8];
            float4 bv1 = *(const float4*)&Bs[cur][kk][tx * 8 + 4];
            float ar[8]  = {av0.x, av0.y, av0.z, av0.w, av1.x, av1.y, av1.z, av1.w};
            float brr[8] = {bv0.x, bv0.y, bv0.z, bv0.w, bv1.x, bv1.y, bv1.z, bv1.w};
#pragma unroll
            for (int i = 0; i < 8; i++)
#pragma unroll
                for (int j = 0; j < 8; j++)
                    acc[i][j] += ar[i] * brr[j];
        }
        if (more) {
            if (reluB) {
                nb0.x = fmaxf(nb0.x, 0.f); nb0.y = fmaxf(nb0.y, 0.f);
                nb0.z = fmaxf(nb0.z, 0.f); nb0.w = fmaxf(nb0.w, 0.f);
                nb1.x = fmaxf(nb1.x, 0.f); nb1.y = fmaxf(nb1.y, 0.f);
                nb1.z = fmaxf(nb1.z, 0.f); nb1.w = fmaxf(nb1.w, 0.f);
            }
            int nxt = cur ^ 1;
            As[nxt][akoff + 0][arow] = na0.x; As[nxt][akoff + 1][arow] = na0.y;
            As[nxt][akoff + 2][arow] = na0.z; As[nxt][akoff + 3][arow] = na0.w;
            As[nxt][akoff + 4][arow] = na1.x; As[nxt][akoff + 5][arow] = na1.y;
            As[nxt][akoff + 6][arow] = na1.z; As[nxt][akoff + 7][arow] = na1.w;
            *(float4*)&Bs[nxt][bk][bcoff]     = nb0;
            *(float4*)&Bs[nxt][bk][bcoff + 4] = nb1;
            cur = nxt;
        }
    }

    if (ga.accum[e]) {
#pragma unroll
        for (int i = 0; i < 8; i++) {
            float* crow = Cm + (long)(ty * 8 + i) * HW + tx * 8;
#pragma unroll
            for (int j = 0; j < 8; j++)
                atomicAdd(&crow[j], scale * acc[i][j]);
        }
    } else {
#pragma unroll
        for (int i = 0; i < 8; i++) {
            float* crow = Cm + (long)(ty * 8 + i) * HW + tx * 8;
            float4 v0 = make_float4(scale * acc[i][0], scale * acc[i][1],
                                    scale * acc[i][2], scale * acc[i][3]);
            float4 v1 = make_float4(scale * acc[i][4], scale * acc[i][5],
                                    scale * acc[i][6], scale * acc[i][7]);
            *(float4*)&crow[0] = v0;
            *(float4*)&crow[4] = v1;
        }
    }
}

// ---------------- host orchestration ----------------
extern "C" void kernel_launch(void* const* d_in, const int* in_sizes, int n_in,
                              void* d_out, int out_size) {
    const float* s0r   = (const float*)d_in[0];
    const float* s1r   = (const float*)d_in[1];
    const float* gates = (const float*)d_in[2];
    const float* pre0  = (const float*)d_in[3];
    const float* pre1  = (const float*)d_in[4];
    const float* s3d1  = (const float*)d_in[5];
    const float* s3p1  = (const float*)d_in[6];
    const float* s3d2  = (const float*)d_in[7];
    const float* s3p2  = (const float*)d_in[8];
    const float* s5d1  = (const float*)d_in[9];
    const float* s5p1  = (const float*)d_in[10];
    const float* s5d2  = (const float*)d_in[11];
    const float* s5p2  = (const float*)d_in[12];
    const float* d3d   = (const float*)d_in[13];
    const float* d3p   = (const float*)d_in[14];
    const float* d5d   = (const float*)d_in[15];
    const float* d5p   = (const float*)d_in[16];
    float* out = (float*)d_out;

    float *ps0, *ps1, *pt, *pu, *pp;
    cudaGetSymbolAddress((void**)&ps0, g_s0);
    cudaGetSymbolAddress((void**)&ps1, g_s1);
    cudaGetSymbolAddress((void**)&pt,  g_t);
    cudaGetSymbolAddress((void**)&pu,  g_u);
    cudaGetSymbolAddress((void**)&pp,  g_pw);

    gate_kernel<<<2, 256>>>(gates, pp);

    // preprocess: s0/s1 -> states 0/1 (ReLU -> 1x1 conv 512->128 -> BN)
    {
        GemmArgs pa = {};
        pa.K = CIN; pa.reluB = 1;
        pa.A[0] = pre0; pa.B[0] = s0r; pa.Cp[0] = ps0; pa.P[0] = nullptr;
        pa.cscale[0] = BNS; pa.bsB[0] = (long)CIN * HW; pa.bsC[0] = PLANE;
        pa.A[1] = pre1; pa.B[1] = s1r; pa.Cp[1] = ps1; pa.P[1] = nullptr;
        pa.cscale[1] = BNS; pa.bsB[1] = (long)CIN * HW; pa.bsC[1] = PLANE;
        gemm128<<<dim3(8, NB, 2), 256>>>(pa);
    }

    struct StateDesc { float* p; long bs; };
    StateDesc st[6] = {
        {ps0, (long)PLANE}, {ps1, (long)PLANE},
        {out,             512L * HW}, {out + PLANE,     512L * HW},
        {out + 2 * PLANE, 512L * HW}, {out + 3 * PLANE, 512L * HW}
    };

    const float* dw1w[4]  = {s3d1, s5d1, d3d, d5d};
    const long   dw1sz[4] = {9, 25, 9, 25};
    const int    dwk[4]   = {3, 5, 3, 5};
    const int    dwdil[4] = {1, 1, 2, 2};
    const float* pw1w[4]  = {s3p1, s5p1, d3p, d5p};

    int offset = 0;
    for (int i = 0; i < 4; i++) {
        int nj = 2 + i;
        StateDesc dst = st[2 + i];

        // pools + skip, all j in one launch
        PoolArgs pa = {};
        for (int j = 0; j < nj; j++) {
            pa.X[j] = st[j].p; pa.bsX[j] = st[j].bs;
            pa.P[j] = pp + (long)(offset + j) * NB * 8;
        }
        pa.O = dst.p; pa.bsO = dst.bs; pa.nj = nj;
        pool_kernel<<<dim3(CC, NB), 256>>>(pa);

        // dw1: all (j, branch)
        DwArgs d1 = {};
        for (int j = 0; j < nj; j++) {
            int m = offset + j;
            const float* gp = pp + (long)m * NB * 8;
            for (int br = 0; br < 4; br++) {
                int e = j * 4 + br;
                d1.X[e] = st[j].p; d1.bsX[e] = st[j].bs;
                d1.W[e] = dw1w[br] + (long)m * CC * dw1sz[br];
                d1.Y[e] = pt + (long)e * NBPLANE;
                d1.P[e] = gp + 4 + br;
                d1.ks[e] = dwk[br]; d1.dil[e] = dwdil[br];
            }
        }
        dw_kernel<<<dim3(CC, NB, nj * 4), 256>>>(d1);

        // gemm1: sep pw1 -> u (store), dil pw -> dst (scaled atomic accumulate)
        GemmArgs g1 = {};
        g1.K = CC; g1.reluB = 0;
        for (int j = 0; j < nj; j++) {
            int m = offset + j;
            const float* gp = pp + (long)m * NB * 8;
            for (int br = 0; br < 4; br++) {
                int e = j * 4 + br;
                g1.A[e] = pw1w[br] + (long)m * CC * CC;
                g1.B[e] = pt + (long)e * NBPLANE;
                g1.P[e] = gp + 4 + br;
                g1.cscale[e] = BNS;
                g1.bsB[e] = PLANE;
                if (br < 2) {
                    g1.Cp[e] = pu + (long)(j * 2 + br) * NBPLANE;
                    g1.byP[e] = 0; g1.accum[e] = 0; g1.bsC[e] = PLANE;
                } else {
                    g1.Cp[e] = dst.p;
                    g1.byP[e] = 1; g1.accum[e] = 1; g1.bsC[e] = dst.bs;
                }
            }
        }
        gemm128<<<dim3(8, NB, nj * 4), 256>>>(g1);

        // dw2: sep3_dw2 / sep5_dw2 on relu(u); outputs alias pt slots (already consumed)
        DwArgs d2 = {};
        for (int j = 0; j < nj; j++) {
            int m = offset + j;
            const float* gp = pp + (long)m * NB * 8;
            for (int br = 0; br < 2; br++) {
                int e = j * 2 + br;
                d2.X[e] = pu + (long)e * NBPLANE; d2.bsX[e] = PLANE;
                d2.W[e] = (br == 0 ? s3d2 + (long)m * CC * 9 : s5d2 + (long)m * CC * 25);
                d2.Y[e] = pt + (long)(j * 4 + br) * NBPLANE;
                d2.P[e] = gp + 4 + br;
                d2.ks[e] = (br == 0 ? 3 : 5); d2.dil[e] = 1;
            }
        }
        dw_kernel<<<dim3(CC, NB, nj * 2), 256>>>(d2);

        // gemm2: sep pw2 -> dst (scaled atomic accumulate)
        GemmArgs g2 = {};
        g2.K = CC; g2.reluB = 0;
        for (int j = 0; j < nj; j++) {
            int m = offset + j;
            const float* gp = pp + (long)m * NB * 8;
            for (int br = 0; br < 2; br++) {
                int e = j * 2 + br;
                g2.A[e] = (br == 0 ? s3p2 + (long)m * CC * CC : s5p2 + (long)m * CC * CC);
                g2.B[e] = pt + (long)(j * 4 + br) * NBPLANE;
                g2.Cp[e] = dst.p;
                g2.P[e] = gp + 4 + br;
                g2.cscale[e] = BNS; g2.byP[e] = 1; g2.accum[e] = 1;
                g2.bsB[e] = PLANE; g2.bsC[e] = dst.bs;
            }
        }
        gemm128<<<dim3(8, NB, nj * 2), 256>>>(g2);

        offset += nj;
    }
}